// round 15
// baseline (speedup 1.0000x reference)
#include <cuda_runtime.h>
#include <math.h>

// Problem constants
#define B   32
#define C   512
#define HW  3136          // 56*56
#define HW4 784           // HW / 4 (float4)
#define HID 32            // C / RED
#define KSEL 256          // C / 2
#define NROW (B * C)      // 16384 rows

// Allocation-free scratch (device globals)
__device__ float g_y[NROW];     // pooled mean+max per (b,c)
__device__ float g_map[NROW];   // final per-channel multiplier

// Force a v4 load that ptxas cannot sink/reorder past the batch.
__device__ __forceinline__ float4 ldg_v4(const float4* p) {
    float4 v;
    asm volatile("ld.global.nc.v4.f32 {%0,%1,%2,%3}, [%4];"
                 : "=f"(v.x), "=f"(v.y), "=f"(v.z), "=f"(v.w) : "l"(p));
    return v;
}

// ---------------------------------------------------------------------------
// Kernel 1: per-(b,c) mean + max over 3136 spatial elements.
// One WARP per row. 8 loads issued back-to-back per lane. (At LTS ceiling.)
// ---------------------------------------------------------------------------
__global__ __launch_bounds__(256) void pool_kernel(const float* __restrict__ x) {
    const int row = blockIdx.x * 8 + (threadIdx.x >> 5);
    const int lid = threadIdx.x & 31;
    const float4* __restrict__ r =
        reinterpret_cast<const float4*>(x + (size_t)row * HW);

    float s = 0.0f;
    float m = -INFINITY;

    int i = lid;
    #pragma unroll 1
    for (; i + 224 < HW4; i += 256) {
        float4 v0 = ldg_v4(r + i);
        float4 v1 = ldg_v4(r + i + 32);
        float4 v2 = ldg_v4(r + i + 64);
        float4 v3 = ldg_v4(r + i + 96);
        float4 v4 = ldg_v4(r + i + 128);
        float4 v5 = ldg_v4(r + i + 160);
        float4 v6 = ldg_v4(r + i + 192);
        float4 v7 = ldg_v4(r + i + 224);
        s += (v0.x + v0.y) + (v0.z + v0.w);
        s += (v1.x + v1.y) + (v1.z + v1.w);
        s += (v2.x + v2.y) + (v2.z + v2.w);
        s += (v3.x + v3.y) + (v3.z + v3.w);
        s += (v4.x + v4.y) + (v4.z + v4.w);
        s += (v5.x + v5.y) + (v5.z + v5.w);
        s += (v6.x + v6.y) + (v6.z + v6.w);
        s += (v7.x + v7.y) + (v7.z + v7.w);
        m = fmaxf(m, fmaxf(fmaxf(v0.x, v0.y), fmaxf(v0.z, v0.w)));
        m = fmaxf(m, fmaxf(fmaxf(v1.x, v1.y), fmaxf(v1.z, v1.w)));
        m = fmaxf(m, fmaxf(fmaxf(v2.x, v2.y), fmaxf(v2.z, v2.w)));
        m = fmaxf(m, fmaxf(fmaxf(v3.x, v3.y), fmaxf(v3.z, v3.w)));
        m = fmaxf(m, fmaxf(fmaxf(v4.x, v4.y), fmaxf(v4.z, v4.w)));
        m = fmaxf(m, fmaxf(fmaxf(v5.x, v5.y), fmaxf(v5.z, v5.w)));
        m = fmaxf(m, fmaxf(fmaxf(v6.x, v6.y), fmaxf(v6.z, v6.w)));
        m = fmaxf(m, fmaxf(fmaxf(v7.x, v7.y), fmaxf(v7.z, v7.w)));
    }
    if (i < HW4) {   // tail: lanes 0..15
        float4 a = ldg_v4(r + i);
        s += (a.x + a.y) + (a.z + a.w);
        m = fmaxf(m, fmaxf(fmaxf(a.x, a.y), fmaxf(a.z, a.w)));
    }

    #pragma unroll
    for (int off = 16; off > 0; off >>= 1) {
        s += __shfl_xor_sync(0xFFFFFFFFu, s, off);
        m = fmaxf(m, __shfl_xor_sync(0xFFFFFFFFu, m, off));
    }
    if (lid == 0)
        g_y[row] = s * (1.0f / (float)HW) + m;
}

// ---------------------------------------------------------------------------
// Kernel 2: tiny MLP + sigmoid + rank-mask + rand gate.
// One block per batch, 512 threads (one per channel).
// ---------------------------------------------------------------------------
__global__ __launch_bounds__(512) void mlp_mask_kernel(
    const float* __restrict__ w1, const float* __restrict__ b1,
    const float* __restrict__ prelu_a,
    const float* __restrict__ w2, const float* __restrict__ b2,
    const float* __restrict__ rand)
{
    const int b = blockIdx.x;
    const int t = threadIdx.x;
    const int wid = t >> 5;     // warp 0..15
    const int lid = t & 31;

    __shared__ __align__(16) float y_s[C];
    __shared__ __align__(16) float hpart[16][HID];
    __shared__ __align__(16) float h_s[HID];
    __shared__ __align__(16) float y2_s[C];

    y_s[t] = g_y[b * C + t];
    __syncthreads();

    // h partials: warp w covers channels [32w, 32w+32), lane j = hidden unit j.
    {
        float acc = 0.0f;
        const int c0 = wid * 32;
        #pragma unroll
        for (int k = 0; k < 32; k++) {
            const int c = c0 + k;
            acc = fmaf(y_s[c], __ldg(&w1[c * HID + lid]), acc);
        }
        hpart[wid][lid] = acc;
    }
    __syncthreads();

    if (t < HID) {
        float acc = b1[t];
        #pragma unroll
        for (int w = 0; w < 16; w++) acc += hpart[w][t];
        const float a = prelu_a[0];
        h_s[t] = (acc >= 0.0f) ? acc : a * acc;
    }
    __syncthreads();

    float acc = __ldg(&b2[t]);
    #pragma unroll
    for (int j = 0; j < HID; j++)
        acc = fmaf(h_s[j], __ldg(&w2[j * C + t]), acc);
    const float y2 = 1.0f / (1.0f + expf(-acc));
    y2_s[t] = y2;
    __syncthreads();

    // rank count: mask_t = (#{i : y2_i > y2_t} >= K)
    int g = 0;
    const float4* __restrict__ yv = reinterpret_cast<const float4*>(y2_s);
    #pragma unroll 4
    for (int i = 0; i < C / 4; i++) {
        float4 q = yv[i];
        g += (q.x > y2) + (q.y > y2) + (q.z > y2) + (q.w > y2);
    }

    const bool below = (g >= KSEL);
    const bool rb = (__ldg(&rand[b * C + t]) - 0.5f < 0.0f);
    const float fm = rb ? (below ? y2 : 0.0f) : y2;
    g_map[b * C + t] = fm;
}

// ---------------------------------------------------------------------------
// Kernel 3: out = x * final_map.
// WARP-PER-ROW (pool's proven geometry): 2048 CTAs x 8 warps, 4-deep batched
// streaming loads/stores per lane, reversed row order, warp-level zero-skip.
// 784 = 6*128 + 16: 6 batches of 4 per lane + 16-lane tail.
// ---------------------------------------------------------------------------
__global__ __launch_bounds__(256) void scale_kernel(
    const float* __restrict__ x, float* __restrict__ out)
{
    const int row = (NROW - 1) - (blockIdx.x * 8 + (threadIdx.x >> 5));
    const int lid = threadIdx.x & 31;
    const float f = g_map[row];
    float4* __restrict__ oo =
        reinterpret_cast<float4*>(out + (size_t)row * HW);

    if (f == 0.0f) {
        const float4 z = make_float4(0.0f, 0.0f, 0.0f, 0.0f);
        int i = lid;
        #pragma unroll 1
        for (; i + 96 < HW4; i += 128) {
            __stcs(&oo[i],      z);
            __stcs(&oo[i + 32], z);
            __stcs(&oo[i + 64], z);
            __stcs(&oo[i + 96], z);
        }
        if (i < HW4) __stcs(&oo[i], z);
        return;
    }

    const float4* __restrict__ xi =
        reinterpret_cast<const float4*>(x + (size_t)row * HW);

    int i = lid;
    #pragma unroll 1
    for (; i + 96 < HW4; i += 128) {
        float4 a = __ldcs(&xi[i]);
        float4 b = __ldcs(&xi[i + 32]);
        float4 c = __ldcs(&xi[i + 64]);
        float4 d = __ldcs(&xi[i + 96]);
        a.x *= f; a.y *= f; a.z *= f; a.w *= f;
        b.x *= f; b.y *= f; b.z *= f; b.w *= f;
        c.x *= f; c.y *= f; c.z *= f; c.w *= f;
        d.x *= f; d.y *= f; d.z *= f; d.w *= f;
        __stcs(&oo[i],      a);
        __stcs(&oo[i + 32], b);
        __stcs(&oo[i + 64], c);
        __stcs(&oo[i + 96], d);
    }
    if (i < HW4) {   // tail: lanes 0..15
        float4 a = __ldcs(&xi[i]);
        a.x *= f; a.y *= f; a.z *= f; a.w *= f;
        __stcs(&oo[i], a);
    }
}

// ---------------------------------------------------------------------------
// Launch. Inputs (metadata order): x, w1, b1, prelu_a, w2, b2, rand
// ---------------------------------------------------------------------------
extern "C" void kernel_launch(void* const* d_in, const int* in_sizes, int n_in,
                              void* d_out, int out_size) {
    const float* x       = (const float*)d_in[0];
    const float* w1      = (const float*)d_in[1];
    const float* b1      = (const float*)d_in[2];
    const float* prelu_a = (const float*)d_in[3];
    const float* w2      = (const float*)d_in[4];
    const float* b2      = (const float*)d_in[5];
    const float* rand    = (const float*)d_in[6];
    float* out = (float*)d_out;

    pool_kernel<<<NROW / 8, 256>>>(x);
    mlp_mask_kernel<<<B, C>>>(w1, b1, prelu_a, w2, b2, rand);
    scale_kernel<<<NROW / 8, 256>>>(x, out);
}